// round 4
// baseline (speedup 1.0000x reference)
#include <cuda_runtime.h>
#include <math.h>

// ---------------- problem constants ----------------
static constexpr int F   = 15;
static constexpr int H   = 128;
static constexpr int L   = 12;
static constexpr int NB  = 16;
static constexpr int M   = 3 * NB - 1;   // 47
static constexpr int FM  = F * M;        // 705
static constexpr int B   = 65536;

static constexpr float TAIL = 3.0f;
static constexpr float MINP = 0.001f;

// ---------------- kernel tiling ----------------
static constexpr int TS   = 128;   // samples per block
static constexpr int NT   = 256;   // threads per block
static constexpr int SST  = 132;   // col-major sample stride (mult of 4, !mult of 32)
static constexpr int WSTR = 144;   // weight / raw row stride (>=141, mult of 4)
static constexpr int KH   = 64;    // k-half for weight staging

// smem layout (floats):
//   hs   [H][SST]    16896   (activations, col-major: [j][s])
//   buf2 max(t colmajor [H][SST]=16896, raw rowmajor [TS][WSTR]=18432) = 18432
//   ws   [KH][WSTR]   9216
//   xs   [16][SST]    2112   (x, col-major: [f][s])
//   lds  [TS*3]        384
static constexpr int HS_FL   = H * SST;
static constexpr int BUF2_FL = TS * WSTR;      // 18432 (covers both uses)
static constexpr int WS_FL   = KH * WSTR;
static constexpr int XS_FL   = 16 * SST;
static constexpr int SMEM_FLOATS = HS_FL + BUF2_FL + WS_FL + XS_FL + TS * 3;
static constexpr int SMEM_BYTES  = SMEM_FLOATS * 4;   // 188,160 B -> 1 block/SM

// ---------------- device scratch ----------------
__device__ float g_WiT[L * F * H];       // [l][f][i]
__device__ float g_WrT[L * 4 * H * H];   // [l][m][j][i]
__device__ float g_WoT[L * H * FM];      // [l][j][o]
__device__ float g_x  [(size_t)B * F];
__device__ float g_ld [B];

// ---------------- premask + transpose ----------------
__global__ void premask_kernel(const float* __restrict__ Wi,
                               const float* __restrict__ Wr,
                               const float* __restrict__ Wo)
{
    int tid = blockIdx.x * blockDim.x + threadIdx.x;
    int nth = gridDim.x * blockDim.x;

    for (int idx = tid; idx < L * F * H; idx += nth) {
        int l = idx / (F * H);
        int r = idx % (F * H);
        int f = r / H;
        int i = r % H;
        float mk = ((i % (F - 1)) >= f) ? 1.0f : 0.0f;
        g_WiT[idx] = Wi[(l * H + i) * F + f] * mk;
    }
    for (int idx = tid; idx < L * 4 * H * H; idx += nth) {
        int lm = idx / (H * H);
        int r  = idx % (H * H);
        int j  = r / H;
        int i  = r % H;
        float mk = ((i % (F - 1)) >= (j % (F - 1))) ? 1.0f : 0.0f;
        g_WrT[idx] = Wr[((size_t)lm * H + i) * H + j] * mk;
    }
    for (int idx = tid; idx < L * H * FM; idx += nth) {
        int l = idx / (H * FM);
        int r = idx % (H * FM);
        int j = r / FM;
        int o = r % FM;
        float mk = ((o / M) > (j % (F - 1))) ? 1.0f : 0.0f;
        g_WoT[idx] = Wo[((size_t)l * FM + o) * H + j] * mk;
    }
}

// ---------------- packed fp32 helpers ----------------
typedef unsigned long long ull;

__device__ __forceinline__ ull pack2(float lo, float hi) {
    ull r; asm("mov.b64 %0, {%1,%2};" : "=l"(r) : "f"(lo), "f"(hi)); return r;
}
__device__ __forceinline__ void unpack2(ull v, float& lo, float& hi) {
    asm("mov.b64 {%0,%1}, %2;" : "=f"(lo), "=f"(hi) : "l"(v));
}
__device__ __forceinline__ ull ffma2(ull a, ull b, ull c) {
    ull d; asm("fma.rn.f32x2 %0, %1, %2, %3;" : "=l"(d) : "l"(a), "l"(b), "l"(c)); return d;
}
__device__ __forceinline__ float softplusf(float v) {
    return fmaxf(v, 0.0f) + log1pf(expf(-fabsf(v)));
}

// C (=|+=) [bias] + sum_{j<K} act(A[j][s]) * W[j][c]
// A col-major (stride lda). W smem row stride WSTR. Tile: 4 samples x 16 cols.
// CMAJ: C col-major [c][s] stride ldc.  else row-major [s][c] stride ldc.
template <bool RELU, bool ACCUM, bool BIAS, bool CMAJ>
__device__ __forceinline__ void gemm2(const float* __restrict__ A, int lda,
                                      const float* __restrict__ W,
                                      float*       __restrict__ C, int ldc,
                                      const float* __restrict__ bias,
                                      int K, int NC)
{
    const int NCG   = (NC + 15) / 16;
    const int UNITS = (TS / 4) * NCG;

    for (int t = threadIdx.x; t < UNITS; t += NT) {
        const int s0 = (t / NCG) * 4;
        const int c0 = (t % NCG) * 16;

        ull acc[4][8];
        #pragma unroll
        for (int i = 0; i < 8; i++) {
            float lo = 0.0f, hi = 0.0f;
            if (BIAS) {
                int c = c0 + 2 * i;
                if (c     < NC) lo = bias[c];
                if (c + 1 < NC) hi = bias[c + 1];
            }
            ull bv = pack2(lo, hi);
            #pragma unroll
            for (int k = 0; k < 4; k++) acc[k][i] = bv;
        }

        const float* arow = A + s0;
        const float* wrow = W + c0;

        #pragma unroll 4
        for (int j = 0; j < K; j++) {
            float4 av = *(const float4*)(arow);
            arow += lda;
            ulonglong2 wA = *(const ulonglong2*)(wrow);
            ulonglong2 wB = *(const ulonglong2*)(wrow + 4);
            ulonglong2 wC = *(const ulonglong2*)(wrow + 8);
            ulonglong2 wD = *(const ulonglong2*)(wrow + 12);
            wrow += WSTR;

            float v0 = av.x, v1 = av.y, v2 = av.z, v3 = av.w;
            if (RELU) {
                v0 = fmaxf(v0, 0.0f); v1 = fmaxf(v1, 0.0f);
                v2 = fmaxf(v2, 0.0f); v3 = fmaxf(v3, 0.0f);
            }
            ull p0 = pack2(v0, v0), p1 = pack2(v1, v1);
            ull p2 = pack2(v2, v2), p3 = pack2(v3, v3);

            acc[0][0] = ffma2(p0, wA.x, acc[0][0]);
            acc[0][1] = ffma2(p0, wA.y, acc[0][1]);
            acc[0][2] = ffma2(p0, wB.x, acc[0][2]);
            acc[0][3] = ffma2(p0, wB.y, acc[0][3]);
            acc[0][4] = ffma2(p0, wC.x, acc[0][4]);
            acc[0][5] = ffma2(p0, wC.y, acc[0][5]);
            acc[0][6] = ffma2(p0, wD.x, acc[0][6]);
            acc[0][7] = ffma2(p0, wD.y, acc[0][7]);

            acc[1][0] = ffma2(p1, wA.x, acc[1][0]);
            acc[1][1] = ffma2(p1, wA.y, acc[1][1]);
            acc[1][2] = ffma2(p1, wB.x, acc[1][2]);
            acc[1][3] = ffma2(p1, wB.y, acc[1][3]);
            acc[1][4] = ffma2(p1, wC.x, acc[1][4]);
            acc[1][5] = ffma2(p1, wC.y, acc[1][5]);
            acc[1][6] = ffma2(p1, wD.x, acc[1][6]);
            acc[1][7] = ffma2(p1, wD.y, acc[1][7]);

            acc[2][0] = ffma2(p2, wA.x, acc[2][0]);
            acc[2][1] = ffma2(p2, wA.y, acc[2][1]);
            acc[2][2] = ffma2(p2, wB.x, acc[2][2]);
            acc[2][3] = ffma2(p2, wB.y, acc[2][3]);
            acc[2][4] = ffma2(p2, wC.x, acc[2][4]);
            acc[2][5] = ffma2(p2, wC.y, acc[2][5]);
            acc[2][6] = ffma2(p2, wD.x, acc[2][6]);
            acc[2][7] = ffma2(p2, wD.y, acc[2][7]);

            acc[3][0] = ffma2(p3, wA.x, acc[3][0]);
            acc[3][1] = ffma2(p3, wA.y, acc[3][1]);
            acc[3][2] = ffma2(p3, wB.x, acc[3][2]);
            acc[3][3] = ffma2(p3, wB.y, acc[3][3]);
            acc[3][4] = ffma2(p3, wC.x, acc[3][4]);
            acc[3][5] = ffma2(p3, wC.y, acc[3][5]);
            acc[3][6] = ffma2(p3, wD.x, acc[3][6]);
            acc[3][7] = ffma2(p3, wD.y, acc[3][7]);
        }

        if (CMAJ) {
            #pragma unroll
            for (int i = 0; i < 8; i++) {
                int c = c0 + 2 * i;
                #pragma unroll
                for (int k = 0; k < 4; k++) {
                    float lo, hi;
                    unpack2(acc[k][i], lo, hi);
                    if (c < NC) {
                        float* p = C + c * ldc + s0 + k;
                        if (ACCUM) *p += lo; else *p = lo;
                    }
                    if (c + 1 < NC) {
                        float* p = C + (c + 1) * ldc + s0 + k;
                        if (ACCUM) *p += hi; else *p = hi;
                    }
                }
            }
        } else {
            #pragma unroll
            for (int k = 0; k < 4; k++) {
                float* cp = C + (s0 + k) * ldc + c0;
                #pragma unroll
                for (int i = 0; i < 8; i++) {
                    float lo, hi;
                    unpack2(acc[k][i], lo, hi);
                    int c = c0 + 2 * i;
                    if (c < NC)     { if (ACCUM) cp[2*i]   += lo; else cp[2*i]   = lo; }
                    if (c + 1 < NC) { if (ACCUM) cp[2*i+1] += hi; else cp[2*i+1] = hi; }
                }
            }
        }
    }
}

// ---------------- weight staging ----------------
// residual half: source [j][i] contiguous rows of 128 -> ws[j][WSTR], float4 both sides
__device__ __forceinline__ void stage_res_half(float* __restrict__ ws,
                                               const float* __restrict__ Wsrc,
                                               int j0)
{
    for (int e4 = threadIdx.x; e4 < KH * (H / 4); e4 += NT) {
        int j = e4 >> 5, i4 = e4 & 31;
        *(float4*)(ws + j * WSTR + i4 * 4) =
            *(const float4*)(Wsrc + (size_t)(j0 + j) * H + i4 * 4);
    }
}

// output half: source rows stride FM (unaligned) -> scalar LDG, float4 STS, zero pad
__device__ __forceinline__ void stage_out_half(float* __restrict__ ws,
                                               const float* __restrict__ Wo,
                                               int j0, int base, int nc)
{
    for (int e4 = threadIdx.x; e4 < KH * (WSTR / 4); e4 += NT) {
        int j  = e4 / (WSTR / 4);
        int c4 = (e4 % (WSTR / 4)) * 4;
        const float* src = Wo + (size_t)(j0 + j) * FM + base;
        float4 v;
        v.x = (c4     < nc) ? src[c4]     : 0.0f;
        v.y = (c4 + 1 < nc) ? src[c4 + 1] : 0.0f;
        v.z = (c4 + 2 < nc) ? src[c4 + 2] : 0.0f;
        v.w = (c4 + 3 < nc) ? src[c4 + 3] : 0.0f;
        *(float4*)(ws + j * WSTR + c4) = v;
    }
}

// ---------------- one flow layer ----------------
__global__ void __launch_bounds__(NT, 1)
layer_kernel(const float* __restrict__ x0,
             float* __restrict__ outz,
             float* __restrict__ outld,
             int layer,
             const float* __restrict__ b_init,
             const float* __restrict__ b_res,
             const float* __restrict__ b_out)
{
    extern __shared__ float sm[];
    float* hs   = sm;                  // [H][SST] col-major
    float* buf2 = hs   + HS_FL;        // t: [H][SST] col-major / raw: [TS][WSTR]
    float* ws   = buf2 + BUF2_FL;      // [KH][WSTR]
    float* xs   = ws   + WS_FL;        // [16][SST] col-major
    float* lds4 = xs   + XS_FL;        // [TS*3]

    const int tid = threadIdx.x;
    const int gs0 = blockIdx.x * TS;

    const float* x_in  = (layer == 0)     ? x0   : g_x;
    float*       x_out = (layer == L - 1) ? outz : g_x;

    // load samples (reversed features), store col-major
    for (int e = tid; e < TS * F; e += NT) {
        int s = e / F, f = e % F;
        xs[f * SST + s] = x_in[(size_t)(gs0 + s) * F + (F - 1 - f)];
    }
    for (int u = tid; u < TS * 3; u += NT) lds4[u] = 0.0f;

    // ---- init GEMM: h = xs @ WiT + b_init (K=15) ----
    {
        const float* Wi = g_WiT + (size_t)layer * F * H;
        for (int e4 = tid; e4 < F * (H / 4); e4 += NT) {
            int f = e4 >> 5, i4 = e4 & 31;
            *(float4*)(ws + f * WSTR + i4 * 4) = *(const float4*)(Wi + f * H + i4 * 4);
        }
        __syncthreads();
        gemm2<false, false, true, true>(xs, SST, ws, hs, SST, b_init + layer * H, F, H);
        __syncthreads();
    }

    // ---- two residual blocks ----
    for (int blk = 0; blk < 2; blk++) {
        const float* Wa = g_WrT + ((size_t)layer * 4 + blk * 2) * H * H;
        const float* Wb = Wa + H * H;
        const float* ba = b_res + ((layer * 2 + blk) * 2 + 0) * H;
        const float* bb = b_res + ((layer * 2 + blk) * 2 + 1) * H;

        stage_res_half(ws, Wa, 0);
        __syncthreads();
        gemm2<true, false, true, true>(hs, SST, ws, buf2, SST, ba, KH, H);
        __syncthreads();
        stage_res_half(ws, Wa, KH);
        __syncthreads();
        gemm2<true, true, false, true>(hs + KH * SST, SST, ws, buf2, SST, nullptr, KH, H);
        __syncthreads();

        stage_res_half(ws, Wb, 0);
        __syncthreads();
        gemm2<true, true, true, true>(buf2, SST, ws, hs, SST, bb, KH, H);
        __syncthreads();
        stage_res_half(ws, Wb, KH);
        __syncthreads();
        gemm2<true, true, false, true>(buf2 + KH * SST, SST, ws, hs, SST, nullptr, KH, H);
        __syncthreads();
    }

    // ---- output GEMM + spline, 3 features (141 cols) at a time ----
    const float* Wo = g_WoT + (size_t)layer * H * FM;

    for (int fb = 0; fb < F; fb += 3) {
        const int base = fb * M;
        const int nc   = 3 * M;   // 141

        stage_out_half(ws, Wo, 0, base, nc);
        __syncthreads();
        gemm2<false, false, true, false>(hs, SST, ws, buf2, WSTR,
                                         b_out + (size_t)layer * FM + base, KH, nc);
        __syncthreads();
        stage_out_half(ws, Wo, KH, base, nc);
        __syncthreads();
        gemm2<false, true, false, false>(hs + KH * SST, SST, ws, buf2, WSTR,
                                         nullptr, KH, nc);
        __syncthreads();

        for (int u = tid; u < TS * 3; u += NT) {
            const int sid  = u / 3;
            const int flid = u % 3;
            const float* p = buf2 + sid * WSTR + flid * M;
            int   f  = fb + flid;
            float xv = xs[f * SST + sid];
            float xc = fminf(fmaxf(xv, -TAIL), TAIL);
            bool inside = (xv >= -TAIL) && (xv <= TAIL);

            // widths softmax + knot walk
            float mw = -1e30f;
            #pragma unroll
            for (int i = 0; i < NB; i++) mw = fmaxf(mw, p[i]);
            float Sw = 0.0f;
            #pragma unroll
            for (int i = 0; i < NB; i++) Sw += expf(p[i] - mw);
            float invw = (1.0f - NB * MINP) / Sw;

            float cum = 0.0f;
            int   sel = 0;
            float lo = -TAIL, hi = TAIL;
            bool  gotHi = false;
            #pragma unroll
            for (int i = 0; i < NB; i++) {
                float wi = MINP + expf(p[i] - mw) * invw;
                cum += wi;
                float kv = (i == NB - 1) ? TAIL : fmaf(2.0f * TAIL, cum, -TAIL);
                if (i < NB - 1 && xc >= kv) { sel = i + 1; lo = kv; }
                if (!gotHi && xc < kv)      { hi = kv; gotHi = true; }
            }
            float w_bin = hi - lo;

            // heights softmax + knot gather
            float mh = -1e30f;
            #pragma unroll
            for (int i = 0; i < NB; i++) mh = fmaxf(mh, p[NB + i]);
            float Sh = 0.0f;
            #pragma unroll
            for (int i = 0; i < NB; i++) Sh += expf(p[NB + i] - mh);
            float invh = (1.0f - NB * MINP) / Sh;

            float cumh = 0.0f;
            float chlo = -TAIL, chhi = TAIL;
            #pragma unroll
            for (int i = 0; i < NB; i++) {
                float hv = MINP + expf(p[NB + i] - mh) * invh;
                cumh += hv;
                float kv = (i == NB - 1) ? TAIL : fmaf(2.0f * TAIL, cumh, -TAIL);
                if (i + 1 == sel)     chlo = kv;
                if (i + 1 == sel + 1) chhi = kv;
            }
            float h_bin = chhi - chlo;

            float d0 = (sel == 0)      ? 1.0f : (MINP + softplusf(p[2 * NB + sel - 1]));
            float d1 = (sel == NB - 1) ? 1.0f : (MINP + softplusf(p[2 * NB + sel]));

            float delta = h_bin / w_bin;
            float theta = (xc - lo) / w_bin;
            float omt   = 1.0f - theta;
            float tomt  = theta * omt;
            float th2   = theta * theta;
            float num   = h_bin * (delta * th2 + d0 * tomt);
            float den   = delta + (d0 + d1 - 2.0f * delta) * tomt;
            float y     = chlo + num / den;
            float dnum  = delta * delta * (d1 * th2 + 2.0f * delta * tomt + d0 * omt * omt);
            float lad   = logf(dnum) - 2.0f * logf(den);

            if (!inside) { y = xv; lad = 0.0f; }
            xs[f * SST + sid] = y;
            lds4[u] += lad;
        }
        __syncthreads();
    }

    // ---- write new state / final outputs ----
    for (int e = tid; e < TS * F; e += NT) {
        int s = e / F, f = e % F;
        x_out[(size_t)(gs0 + s) * F + f] = xs[f * SST + s];
    }
    if (tid < TS) {
        int   g    = gs0 + tid;
        float prev = (layer == 0) ? 0.0f : g_ld[g];
        float v    = prev + lds4[tid * 3] + lds4[tid * 3 + 1] + lds4[tid * 3 + 2];
        if (layer == L - 1) outld[g] = v;
        else                g_ld[g]  = v;
    }
}

// ---------------- launch ----------------
extern "C" void kernel_launch(void* const* d_in, const int* in_sizes, int n_in,
                              void* d_out, int out_size)
{
    (void)in_sizes; (void)n_in; (void)out_size;
    const float* x  = (const float*)d_in[0];
    const float* Wi = (const float*)d_in[1];
    const float* bi = (const float*)d_in[2];
    const float* Wr = (const float*)d_in[3];
    const float* br = (const float*)d_in[4];
    const float* Wo = (const float*)d_in[5];
    const float* bo = (const float*)d_in[6];
    float* outz  = (float*)d_out;
    float* outld = (float*)d_out + (size_t)B * F;

    cudaFuncSetAttribute(layer_kernel,
                         cudaFuncAttributeMaxDynamicSharedMemorySize, SMEM_BYTES);

    premask_kernel<<<512, 256>>>(Wi, Wr, Wo);

    for (int l = 0; l < L; l++) {
        layer_kernel<<<B / TS, NT, SMEM_BYTES>>>(x, outz, outld, l, bi, br, bo);
    }
}